// round 3
// baseline (speedup 1.0000x reference)
#include <cuda_runtime.h>
#include <math.h>

#define BSZ   8
#define TSEQ  2048
#define CDIM  1024
#define HD    64

typedef unsigned long long ull;

// scratch for projected q, k, v  (4 MB each)
__device__ float g_q[BSZ * TSEQ * HD];
__device__ float g_k[BSZ * TSEQ * HD];
__device__ float g_v[BSZ * TSEQ * HD];

// ---- packed f32x2 helpers (sm_103a dual-rate fp32) -------------------------
__device__ __forceinline__ ull pk2(float lo, float hi) {
    ull r; asm("mov.b64 %0, {%1, %2};" : "=l"(r) : "f"(lo), "f"(hi)); return r;
}
__device__ __forceinline__ ull dup2(float v) { return pk2(v, v); }
__device__ __forceinline__ ull ffma2(ull a, ull b, ull c) {
    ull d; asm("fma.rn.f32x2 %0, %1, %2, %3;" : "=l"(d) : "l"(a), "l"(b), "l"(c)); return d;
}
__device__ __forceinline__ ull fmul2(ull a, ull b) {
    ull d; asm("mul.rn.f32x2 %0, %1, %2;" : "=l"(d) : "l"(a), "l"(b)); return d;
}
__device__ __forceinline__ float2 up2(ull v) {
    float lo, hi; asm("mov.b64 {%0, %1}, %2;" : "=f"(lo), "=f"(hi) : "l"(v));
    float2 f; f.x = lo; f.y = hi; return f;
}

// ---------------------------------------------------------------------------
// Kernel 1: QKV projection.  kqv = x @ W + b, bn: 0=k, 1=q, 2=v.
// M=16384, N=192(3x64), K=1024. BM=128, BN=64, BK=16, 256 threads, 8x4 tile.
// Double-buffered smem, packed-A LDS.64, FFMA2 inner loop.
// ---------------------------------------------------------------------------
__global__ __launch_bounds__(256) void qkv_proj_kernel(
    const float* __restrict__ x,
    const float* __restrict__ W,
    const float* __restrict__ b)
{
    __shared__ float As[2][16][132];   // [buf][k][row]
    __shared__ float Bs[2][16][68];    // [buf][k][col]

    const int bm  = blockIdx.x;
    const int bn  = blockIdx.y;
    const int tid = threadIdx.x;

    const int tr = tid >> 4;
    const int tc = tid & 15;
    const int row0 = tr * 8;
    const int col0 = tc * 4;

    const float* xblk = x + (size_t)bm * 128 * CDIM;
    const float* wblk = W + bn * 64;

    // per-thread load coordinates
    const int lr0 = tid >> 2;            // A row for slice 0 (0..63)
    const int lkk = (tid & 3) * 4;       // A k-offset (0,4,8,12)
    const int bkr = tid >> 4;            // B k-row (0..15)
    const int bnc = (tid & 15) * 4;      // B col (0..60)

    ull acc2[4][4];
#pragma unroll
    for (int i = 0; i < 4; i++)
#pragma unroll
        for (int j = 0; j < 4; j++) acc2[i][j] = 0ULL;

    // ---- load chunk 0 into buffer 0 ----
    {
        float4 a0 = *reinterpret_cast<const float4*>(xblk + (size_t)lr0 * CDIM + lkk);
        float4 a1 = *reinterpret_cast<const float4*>(xblk + (size_t)(lr0 + 64) * CDIM + lkk);
        float4 bw = *reinterpret_cast<const float4*>(wblk + (size_t)bkr * 192 + bnc);
        As[0][lkk + 0][lr0] = a0.x; As[0][lkk + 1][lr0] = a0.y;
        As[0][lkk + 2][lr0] = a0.z; As[0][lkk + 3][lr0] = a0.w;
        As[0][lkk + 0][lr0 + 64] = a1.x; As[0][lkk + 1][lr0 + 64] = a1.y;
        As[0][lkk + 2][lr0 + 64] = a1.z; As[0][lkk + 3][lr0 + 64] = a1.w;
        *reinterpret_cast<float4*>(&Bs[0][bkr][bnc]) = bw;
    }
    __syncthreads();

    for (int c = 0; c < 64; c++) {
        const int cur = c & 1;
        // prefetch next chunk into the other buffer
        if (c < 63) {
            const int k0 = (c + 1) * 16;
            float4 a0 = *reinterpret_cast<const float4*>(xblk + (size_t)lr0 * CDIM + k0 + lkk);
            float4 a1 = *reinterpret_cast<const float4*>(xblk + (size_t)(lr0 + 64) * CDIM + k0 + lkk);
            float4 bw = *reinterpret_cast<const float4*>(wblk + (size_t)(k0 + bkr) * 192 + bnc);
            const int nb = cur ^ 1;
            As[nb][lkk + 0][lr0] = a0.x; As[nb][lkk + 1][lr0] = a0.y;
            As[nb][lkk + 2][lr0] = a0.z; As[nb][lkk + 3][lr0] = a0.w;
            As[nb][lkk + 0][lr0 + 64] = a1.x; As[nb][lkk + 1][lr0 + 64] = a1.y;
            As[nb][lkk + 2][lr0 + 64] = a1.z; As[nb][lkk + 3][lr0 + 64] = a1.w;
            *reinterpret_cast<float4*>(&Bs[nb][bkr][bnc]) = bw;
        }

#pragma unroll
        for (int kk = 0; kk < 16; kk++) {
            ull aP0 = *reinterpret_cast<const ull*>(&As[cur][kk][row0 + 0]);
            ull aP1 = *reinterpret_cast<const ull*>(&As[cur][kk][row0 + 2]);
            ull aP2 = *reinterpret_cast<const ull*>(&As[cur][kk][row0 + 4]);
            ull aP3 = *reinterpret_cast<const ull*>(&As[cur][kk][row0 + 6]);
            float4 bf = *reinterpret_cast<const float4*>(&Bs[cur][kk][col0]);
            ull b0 = dup2(bf.x), b1 = dup2(bf.y), b2 = dup2(bf.z), b3 = dup2(bf.w);
            acc2[0][0] = ffma2(aP0, b0, acc2[0][0]);
            acc2[0][1] = ffma2(aP0, b1, acc2[0][1]);
            acc2[0][2] = ffma2(aP0, b2, acc2[0][2]);
            acc2[0][3] = ffma2(aP0, b3, acc2[0][3]);
            acc2[1][0] = ffma2(aP1, b0, acc2[1][0]);
            acc2[1][1] = ffma2(aP1, b1, acc2[1][1]);
            acc2[1][2] = ffma2(aP1, b2, acc2[1][2]);
            acc2[1][3] = ffma2(aP1, b3, acc2[1][3]);
            acc2[2][0] = ffma2(aP2, b0, acc2[2][0]);
            acc2[2][1] = ffma2(aP2, b1, acc2[2][1]);
            acc2[2][2] = ffma2(aP2, b2, acc2[2][2]);
            acc2[2][3] = ffma2(aP2, b3, acc2[2][3]);
            acc2[3][0] = ffma2(aP3, b0, acc2[3][0]);
            acc2[3][1] = ffma2(aP3, b1, acc2[3][1]);
            acc2[3][2] = ffma2(aP3, b2, acc2[3][2]);
            acc2[3][3] = ffma2(aP3, b3, acc2[3][3]);
        }
        __syncthreads();
    }

    float bias[4];
#pragma unroll
    for (int j = 0; j < 4; j++) bias[j] = b[bn * 64 + col0 + j];

    float* outbuf = (bn == 0) ? g_k : (bn == 1) ? g_q : g_v;
#pragma unroll
    for (int i = 0; i < 8; i++) {
        int ip = i >> 1;
        float2 f0 = up2(acc2[ip][0]);
        float2 f1 = up2(acc2[ip][1]);
        float2 f2 = up2(acc2[ip][2]);
        float2 f3 = up2(acc2[ip][3]);
        float4 o;
        o.x = ((i & 1) ? f0.y : f0.x) + bias[0];
        o.y = ((i & 1) ? f1.y : f1.x) + bias[1];
        o.z = ((i & 1) ? f2.y : f2.x) + bias[2];
        o.w = ((i & 1) ? f3.y : f3.x) + bias[3];
        *reinterpret_cast<float4*>(
            outbuf + (size_t)(bm * 128 + row0 + i) * HD + col0) = o;
    }
}

// ---------------------------------------------------------------------------
// Kernel 2: causal flash attention.  Grid 256 blocks (one 64-row q-tile each),
// launched heaviest-first for LPT scheduling + 2-CTA/SM overlap.
// Per key tile: GEMM1 S=Q@K^T (4x4 micro, FFMA2, packed LDS.64 A-loads),
// register softmax, P in its own smem buffer, GEMM2 O+=P@V.  3 syncs/tile.
// ---------------------------------------------------------------------------
__global__ __launch_bounds__(256) void attn_kernel(float* __restrict__ out)
{
    __shared__ float q_s[64][64];   // [d][r^swz], pre-scaled
    __shared__ float k_s[64][64];   // [d][j^swz]
    __shared__ float v_s[64][64];   // [j][c] row-major
    __shared__ float p_s[64][64];   // [j][r^swz]

    const int tid = threadIdx.x;
    const int tr = tid >> 4, tc = tid & 15;
    const int r0 = tr * 4, c0 = tc * 4, j0 = tc * 4;

    const int bid = blockIdx.x;
    const int qt  = 31 - (bid >> 3);     // heavy tiles first
    const int bb  = bid & 7;
    const int qrow0 = qt * 64;

    const float* qg = g_q + ((size_t)bb * TSEQ + qrow0) * HD;
    const float* kg = g_k + (size_t)bb * TSEQ * HD;
    const float* vg = g_v + (size_t)bb * TSEQ * HD;

    // load Q tile transposed + swizzled + pre-scaled
#pragma unroll
    for (int it = 0; it < 4; it++) {
        int idx = it * 256 + tid;
        int r = idx >> 4;
        int d = (idx & 15) << 2;
        float4 v4 = *reinterpret_cast<const float4*>(qg + (size_t)r * HD + d);
        int sw_r = r ^ ((((d) >> 2) & 7) << 2);
        q_s[d + 0][sw_r] = v4.x * 0.125f;
        q_s[d + 1][sw_r] = v4.y * 0.125f;
        q_s[d + 2][sw_r] = v4.z * 0.125f;
        q_s[d + 3][sw_r] = v4.w * 0.125f;
    }

    ull o2[2][4] = {{0ULL,0ULL,0ULL,0ULL},{0ULL,0ULL,0ULL,0ULL}};
    float m[4] = {-1e30f, -1e30f, -1e30f, -1e30f};
    float l[4] = {0.f, 0.f, 0.f, 0.f};

    for (int kt = 0; kt <= qt; kt++) {
        const int t0 = kt * 64;
        __syncthreads();   // k_s, v_s free (prev GEMMs done); q_s stores (first iter)
#pragma unroll
        for (int it = 0; it < 4; it++) {
            int idx = it * 256 + tid;
            int r = idx >> 4;
            int d = (idx & 15) << 2;
            float4 k4 = *reinterpret_cast<const float4*>(
                kg + (size_t)(t0 + r) * HD + d);
            int sw_r = r ^ ((((d) >> 2) & 7) << 2);
            k_s[d + 0][sw_r] = k4.x;
            k_s[d + 1][sw_r] = k4.y;
            k_s[d + 2][sw_r] = k4.z;
            k_s[d + 3][sw_r] = k4.w;
            *reinterpret_cast<float4*>(&v_s[r][d]) =
                *reinterpret_cast<const float4*>(vg + (size_t)(t0 + r) * HD + d);
        }
        __syncthreads();

        // ---- GEMM1: S = Q @ K^T ----
        ull s2[2][4] = {{0ULL,0ULL,0ULL,0ULL},{0ULL,0ULL,0ULL,0ULL}};
#pragma unroll 8
        for (int d = 0; d < 64; d++) {
            int sw  = ((d >> 2) & 7) << 2;
            int r0s = r0 ^ sw;
            ull a01 = *reinterpret_cast<const ull*>(&q_s[d][r0s]);
            ull a23 = *reinterpret_cast<const ull*>(&q_s[d][r0s + 2]);
            float4 bv = *reinterpret_cast<const float4*>(&k_s[d][j0 ^ sw]);
            ull b0 = dup2(bv.x), b1 = dup2(bv.y), b2 = dup2(bv.z), b3 = dup2(bv.w);
            s2[0][0] = ffma2(a01, b0, s2[0][0]);
            s2[0][1] = ffma2(a01, b1, s2[0][1]);
            s2[0][2] = ffma2(a01, b2, s2[0][2]);
            s2[0][3] = ffma2(a01, b3, s2[0][3]);
            s2[1][0] = ffma2(a23, b0, s2[1][0]);
            s2[1][1] = ffma2(a23, b1, s2[1][1]);
            s2[1][2] = ffma2(a23, b2, s2[1][2]);
            s2[1][3] = ffma2(a23, b3, s2[1][3]);
        }

        float s[4][4];
#pragma unroll
        for (int ip = 0; ip < 2; ip++)
#pragma unroll
            for (int j = 0; j < 4; j++) {
                float2 f = up2(s2[ip][j]);
                s[2 * ip + 0][j] = f.x;
                s[2 * ip + 1][j] = f.y;
            }

        if (kt == qt) {   // diagonal tile: causal mask
#pragma unroll
            for (int i = 0; i < 4; i++)
#pragma unroll
                for (int j = 0; j < 4; j++)
                    if (j0 + j > r0 + i) s[i][j] = -1e30f;
        }

        // ---- streaming softmax ----
        float mn[4], corr[4];
#pragma unroll
        for (int i = 0; i < 4; i++) {
            float mx = fmaxf(fmaxf(s[i][0], s[i][1]), fmaxf(s[i][2], s[i][3]));
#pragma unroll
            for (int o = 1; o < 16; o <<= 1)
                mx = fmaxf(mx, __shfl_xor_sync(0xffffffffu, mx, o));
            mn[i]   = fmaxf(m[i], mx);
            corr[i] = __expf(m[i] - mn[i]);
            m[i]    = mn[i];
        }

        const int swp = (tc & 7) << 2;   // swizzle for p rows j0..j0+3
#pragma unroll
        for (int i = 0; i < 4; i++) {
            float r4 = 0.f;
#pragma unroll
            for (int j = 0; j < 4; j++) {
                float e = __expf(s[i][j] - mn[i]);
                r4 += e;
                p_s[j0 + j][(r0 + i) ^ swp] = e;
            }
#pragma unroll
            for (int o = 1; o < 16; o <<= 1)
                r4 += __shfl_xor_sync(0xffffffffu, r4, o);
            l[i] = l[i] * corr[i] + r4;
        }

        ull c01 = pk2(corr[0], corr[1]), c23 = pk2(corr[2], corr[3]);
#pragma unroll
        for (int j = 0; j < 4; j++) {
            o2[0][j] = fmul2(o2[0][j], c01);
            o2[1][j] = fmul2(o2[1][j], c23);
        }
        __syncthreads();   // P visible to all

        // ---- GEMM2: O += P @ V ----
#pragma unroll 8
        for (int j = 0; j < 64; j++) {
            int sw  = ((j >> 2) & 7) << 2;
            int r0s = r0 ^ sw;
            ull a01 = *reinterpret_cast<const ull*>(&p_s[j][r0s]);
            ull a23 = *reinterpret_cast<const ull*>(&p_s[j][r0s + 2]);
            float4 bv = *reinterpret_cast<const float4*>(&v_s[j][c0]);
            ull b0 = dup2(bv.x), b1 = dup2(bv.y), b2 = dup2(bv.z), b3 = dup2(bv.w);
            o2[0][0] = ffma2(a01, b0, o2[0][0]);
            o2[0][1] = ffma2(a01, b1, o2[0][1]);
            o2[0][2] = ffma2(a01, b2, o2[0][2]);
            o2[0][3] = ffma2(a01, b3, o2[0][3]);
            o2[1][0] = ffma2(a23, b0, o2[1][0]);
            o2[1][1] = ffma2(a23, b1, o2[1][1]);
            o2[1][2] = ffma2(a23, b2, o2[1][2]);
            o2[1][3] = ffma2(a23, b3, o2[1][3]);
        }
    }

    // ---- finalize ----
#pragma unroll
    for (int i = 0; i < 4; i++) {
        float inv = 1.f / l[i];
        float2 f0 = up2(o2[i >> 1][0]);
        float2 f1 = up2(o2[i >> 1][1]);
        float2 f2 = up2(o2[i >> 1][2]);
        float2 f3 = up2(o2[i >> 1][3]);
        float4 o;
        o.x = ((i & 1) ? f0.y : f0.x) * inv;
        o.y = ((i & 1) ? f1.y : f1.x) * inv;
        o.z = ((i & 1) ? f2.y : f2.x) * inv;
        o.w = ((i & 1) ? f3.y : f3.x) * inv;
        *reinterpret_cast<float4*>(
            out + ((size_t)bb * TSEQ + qrow0 + r0 + i) * HD + c0) = o;
    }
}

// ---------------------------------------------------------------------------
extern "C" void kernel_launch(void* const* d_in, const int* in_sizes, int n_in,
                              void* d_out, int out_size)
{
    const float* x = (const float*)d_in[0];
    const float* W = (const float*)d_in[1];
    const float* b = (const float*)d_in[2];
    float* out = (float*)d_out;

    (void)in_sizes; (void)n_in; (void)out_size;

    dim3 g1((BSZ * TSEQ) / 128, 3);
    qkv_proj_kernel<<<g1, 256>>>(x, W, b);

    dim3 g2(32 * BSZ);
    attn_kernel<<<g2, 256>>>(out);
}